// round 2
// baseline (speedup 1.0000x reference)
#include <cuda_runtime.h>
#include <math.h>

#define NB 1024
#define NS 100
#define NH 256
#define NL 20000
#define NU 20000
#define NEL 500000
#define NEU 400000

// ---------------- scratch layout (single __device__ global, no allocs) ------
#define OFF_ENCW 0ull                                    // [NL, NH] segment-sum result (loc graph)
#define OFF_EWU  (OFF_ENCW + (size_t)NL * NH)            // [NU, NH] segment-sum result (user graph)
#define OFF_XEMB (OFF_EWU  + (size_t)NU * NH)            // [NB*NS, NH] gathered x_emb
#define OFF_XP   (OFF_XEMB + (size_t)NB * NS * NH)       // [NB*NS, NH] x_emb @ W_ih^T + b_ih
#define OFF_SIM  (OFF_XP   + (size_t)NB * NS * NH)       // [NB, NS] user-loc similarity
#define OFF_WN   (OFF_SIM  + (size_t)NB * NS)            // [NB, NS] normalized weights w_j/denom
#define OFF_FEAT (OFF_WN   + (size_t)NB * NS)            // [NB, 3*NH] concat features
#define OFF_HA   (OFF_FEAT + (size_t)NB * 3 * NH)        // [NB, NH] RNN state ping
#define OFF_HB   (OFF_HA   + (size_t)NB * NH)            // [NB, NH] RNN state pong
#define OFF_NEED (OFF_HB   + (size_t)NB * NH)            // [NU] int flags (reused as float storage)
#define SCRATCH_FLOATS (OFF_NEED + (size_t)NU)

__device__ float g_scratch[SCRATCH_FLOATS];

// ---------------- small utility kernels -------------------------------------
__global__ void zero_k(float* __restrict__ p, int n) {
    int i = blockIdx.x * blockDim.x + threadIdx.x;
    if (i < n) p[i] = 0.0f;
}

__global__ void copy_k(float* __restrict__ dst, const float* __restrict__ src, int n) {
    int i = blockIdx.x * blockDim.x + threadIdx.x;
    if (i < n) dst[i] = src[i];
}

__global__ void mark_k(const int* __restrict__ uid, int* __restrict__ needed) {
    int i = blockIdx.x * blockDim.x + threadIdx.x;
    if (i < NB) needed[uid[i]] = 1;
}

// ---------------- segment-sum scatter: one block per edge -------------------
// out[row[e], :] += vals[e] * emb[col[e], :]
__global__ void scatter_loc_k(const int* __restrict__ row, const int* __restrict__ col,
                              const float* __restrict__ vals, const float* __restrict__ emb,
                              float* __restrict__ out) {
    int e = blockIdx.x;
    int c = threadIdx.x;                 // 256 threads = NH
    int r = row[e], cl = col[e];
    float v = vals[e];
    atomicAdd(out + (size_t)r * NH + c, v * emb[(size_t)cl * NH + c]);
}

// filtered version: skip edges whose destination user is not referenced
__global__ void scatter_usr_k(const int* __restrict__ row, const int* __restrict__ col,
                              const float* __restrict__ vals, const float* __restrict__ emb,
                              float* __restrict__ out, const int* __restrict__ needed) {
    int e = blockIdx.x;
    int r = row[e];
    if (!needed[r]) return;
    int c = threadIdx.x;
    int cl = col[e];
    float v = vals[e];
    atomicAdd(out + (size_t)r * NH + c, v * emb[(size_t)cl * NH + c]);
}

// ---------------- gather x_emb + user-loc similarity ------------------------
// one block per (b,s) pair, 256 threads (one per h)
__global__ void gather_sim_k(const int* __restrict__ fsm, const int* __restrict__ uid,
                             const float* __restrict__ encw, const float* __restrict__ ewu,
                             float* __restrict__ xemb, float* __restrict__ sim) {
    int pair = blockIdx.x;               // b*NS + s
    int h = threadIdx.x;
    int b = pair / NS;
    int loc = fsm[pair];
    float x = encw[(size_t)loc * NH + h];
    xemb[(size_t)pair * NH + h] = x;
    float u = ewu[(size_t)uid[b] * NH + h];
    float d = u - x;
    float ss = d * d;
    __shared__ float red[NH];
    red[h] = ss;
    __syncthreads();
    for (int o = NH / 2; o > 0; o >>= 1) {
        if (h < o) red[h] += red[h + o];
        __syncthreads();
    }
    if (h == 0) sim[pair] = expf(-sqrtf(red[0]));
}

// ---------------- decay weights + normalization -----------------------------
__global__ void weights_k(const float* __restrict__ td, const float* __restrict__ gd,
                          const float* __restrict__ sim, const int* __restrict__ length,
                          float* __restrict__ wn) {
    int b = blockIdx.x;
    int s = threadIdx.x;                 // 128 threads, S=100 valid
    __shared__ float red[128];
    float w = 0.0f;
    if (s < NS) {
        float t = td[b * NS + s];
        float a = (cosf(t * (6.2831853071795864769f / 86400.0f)) + 1.0f) * 0.5f
                  * expf(-t * (0.1f / 86400.0f));
        float bb = expf(-gd[b * NS + s] * 1000.0f);
        w = (a * bb + 1e-10f) * sim[b * NS + s];
        if (s >= length[b]) w = 0.0f;
    }
    red[s] = w;
    __syncthreads();
    for (int o = 64; o > 0; o >>= 1) {
        if (s < o) red[s] += red[s + o];
        __syncthreads();
    }
    float denom = red[0];
    if (s < NS) wn[b * NS + s] = w / denom;
}

// ---------------- generic TN SGEMM: C[M,N] = A[M,K] @ B[N,K]^T --------------
// EPI=0: C = acc + bias[n]
// EPI=1 (RNN step): v = tanh(acc + xp[(m*NS+s)*NH+n] + bias[n]);
//                   C[m*NH+n] = v; feat[m*3NH+n] += v * wn[m*NS+s]
template<int EPI>
__global__ __launch_bounds__(256)
void sgemm_tn(const float* __restrict__ A, const float* __restrict__ Bm,
              float* __restrict__ C, const float* __restrict__ bias,
              int M, int N, int K,
              const float* __restrict__ xp, const float* __restrict__ wn,
              float* __restrict__ feat, int s) {
    const int BM = 64, BN = 64, BK = 16;
    __shared__ __align__(16) float As[BK][BM];
    __shared__ __align__(16) float Bs[BK][BN];

    int tid = threadIdx.x;
    int m0 = blockIdx.y * BM, n0 = blockIdx.x * BN;
    int lr = tid >> 2;                 // 0..63 loader row
    int lc = (tid & 3) << 2;           // 0,4,8,12 loader k-offset
    int ty = tid >> 4;                 // 0..15
    int tx = tid & 15;                 // 0..15

    float acc[4][4];
#pragma unroll
    for (int i = 0; i < 4; i++)
#pragma unroll
        for (int j = 0; j < 4; j++) acc[i][j] = 0.0f;

    for (int k0 = 0; k0 < K; k0 += BK) {
        float4 av = *(const float4*)(A + (size_t)(m0 + lr) * K + k0 + lc);
        As[lc + 0][lr] = av.x; As[lc + 1][lr] = av.y;
        As[lc + 2][lr] = av.z; As[lc + 3][lr] = av.w;
        float4 bv = make_float4(0.f, 0.f, 0.f, 0.f);
        if (n0 + lr < N)
            bv = *(const float4*)(Bm + (size_t)(n0 + lr) * K + k0 + lc);
        Bs[lc + 0][lr] = bv.x; Bs[lc + 1][lr] = bv.y;
        Bs[lc + 2][lr] = bv.z; Bs[lc + 3][lr] = bv.w;
        __syncthreads();
#pragma unroll
        for (int kk = 0; kk < BK; kk++) {
            float4 a4 = *(const float4*)&As[kk][ty * 4];
            float4 b4 = *(const float4*)&Bs[kk][tx * 4];
            float ar[4] = {a4.x, a4.y, a4.z, a4.w};
            float br[4] = {b4.x, b4.y, b4.z, b4.w};
#pragma unroll
            for (int i = 0; i < 4; i++)
#pragma unroll
                for (int j = 0; j < 4; j++) acc[i][j] += ar[i] * br[j];
        }
        __syncthreads();
    }

#pragma unroll
    for (int i = 0; i < 4; i++) {
        int m = m0 + ty * 4 + i;
#pragma unroll
        for (int j = 0; j < 4; j++) {
            int n = n0 + tx * 4 + j;
            if (n < N) {
                float v = acc[i][j];
                if (EPI == 0) {
                    if (bias) v += bias[n];
                    C[(size_t)m * N + n] = v;
                } else {
                    v += xp[((size_t)m * NS + s) * NH + n] + bias[n];
                    v = tanhf(v);
                    C[(size_t)m * NH + n] = v;
                    feat[(size_t)m * 3 * NH + n] += v * wn[m * NS + s];
                }
            }
        }
    }
}

// ---------------- out_w2: weighted emb2 gather ------------------------------
__global__ void outw2_k(const int* __restrict__ fseq, const float* __restrict__ emb2,
                        const float* __restrict__ wn, float* __restrict__ feat) {
    int b = blockIdx.x;
    int h = threadIdx.x;                 // 256
    float acc = 0.0f;
    for (int s = 0; s < NS; s++) {
        int loc = fseq[b * NS + s];
        acc += emb2[(size_t)loc * NH + h] * wn[b * NS + s];
    }
    feat[(size_t)b * 3 * NH + 2 * NH + h] = acc;
}

// ---------------- p_u gather -------------------------------------------------
__global__ void pu_k(const int* __restrict__ uid, const float* __restrict__ user_emb,
                     float* __restrict__ feat) {
    int b = blockIdx.x;
    int h = threadIdx.x;
    feat[(size_t)b * 3 * NH + NH + h] = user_emb[(size_t)uid[b] * NH + h];
}

// ---------------- host launcher ----------------------------------------------
extern "C" void kernel_launch(void* const* d_in, const int* in_sizes, int n_in,
                              void* d_out, int out_size) {
    const int*   full_seq     = (const int*)d_in[0];
    const int*   full_seq_map = (const int*)d_in[1];
    const int*   length       = (const int*)d_in[2];
    const int*   user_id      = (const int*)d_in[3];
    const float* time_delta   = (const float*)d_in[4];
    const float* geo_delta    = (const float*)d_in[5];
    const float* enc_emb      = (const float*)d_in[6];
    const float* user_emb     = (const float*)d_in[7];
    const float* emb2         = (const float*)d_in[8];
    const int*   row_loc      = (const int*)d_in[9];
    const int*   col_loc      = (const int*)d_in[10];
    const float* vals_loc     = (const float*)d_in[11];
    const int*   row_usr      = (const int*)d_in[12];
    const int*   col_usr      = (const int*)d_in[13];
    const float* vals_usr     = (const float*)d_in[14];
    const float* W_ih         = (const float*)d_in[15];
    const float* W_hh         = (const float*)d_in[16];
    const float* b_ih         = (const float*)d_in[17];
    const float* b_hh         = (const float*)d_in[18];
    const float* W1           = (const float*)d_in[19];
    const float* b1           = (const float*)d_in[20];
    const float* h0           = (const float*)d_in[21];
    float* out = (float*)d_out;

    float* base = nullptr;
    cudaGetSymbolAddress((void**)&base, g_scratch);
    float* encw = base + OFF_ENCW;
    float* ewu  = base + OFF_EWU;
    float* xemb = base + OFF_XEMB;
    float* xp   = base + OFF_XP;
    float* sim  = base + OFF_SIM;
    float* wn   = base + OFF_WN;
    float* feat = base + OFF_FEAT;
    float* ha   = base + OFF_HA;
    float* hb   = base + OFF_HB;
    int*   needed = (int*)(base + OFF_NEED);

    // zero accumulators (encw+ewu are contiguous)
    {
        int n = (int)(2 * (size_t)NL * NH);
        zero_k<<<(n + 255) / 256, 256>>>(encw, n);
    }
    zero_k<<<(NB * 3 * NH + 255) / 256, 256>>>(feat, NB * 3 * NH);
    zero_k<<<(NU + 255) / 256, 256>>>((float*)needed, NU);
    mark_k<<<(NB + 255) / 256, 256>>>(user_id, needed);

    // segment sums (atomic scatter)
    scatter_loc_k<<<NEL, NH>>>(row_loc, col_loc, vals_loc, enc_emb, encw);
    scatter_usr_k<<<NEU, NH>>>(row_usr, col_usr, vals_usr, enc_emb, ewu, needed);

    // x_emb gather + similarity
    gather_sim_k<<<NB * NS, NH>>>(full_seq_map, user_id, encw, ewu, xemb, sim);

    // decay weights, masked + normalized
    weights_k<<<NB, 128>>>(time_delta, geo_delta, sim, length, wn);

    // XP = x_emb @ W_ih^T + b_ih  (M=102400, N=256, K=256)
    sgemm_tn<0><<<dim3(NH / 64, (NB * NS) / 64), 256>>>(
        xemb, W_ih, xp, b_ih, NB * NS, NH, NH, nullptr, nullptr, nullptr, 0);

    // RNN init + 100 fused steps (GEMM + tanh + weighted accumulation)
    copy_k<<<(NB * NH + 255) / 256, 256>>>(ha, h0, NB * NH);
    float* hc = ha;
    float* hn = hb;
    for (int s = 0; s < NS; s++) {
        sgemm_tn<1><<<dim3(NH / 64, NB / 64), 256>>>(
            hc, W_hh, hn, b_hh, NB, NH, NH, xp, wn, feat, s);
        float* t = hc; hc = hn; hn = t;
    }

    // out_w2 and p_u into feat
    outw2_k<<<NB, NH>>>(full_seq, emb2, wn, feat);
    pu_k<<<NB, NH>>>(user_id, user_emb, feat);

    // final: out = feat @ W1^T + b1  (M=1024, N=20000, K=768)
    sgemm_tn<0><<<dim3((NL + 63) / 64, NB / 64), 256>>>(
        feat, W1, out, b1, NB, NL, 3 * NH, nullptr, nullptr, nullptr, 0);
}

// round 5
// speedup vs baseline: 1.5173x; 1.5173x over previous
#include <cuda_runtime.h>
#include <cuda_bf16.h>
#include <math.h>
#include <stdint.h>

#define NB 1024
#define NS 100
#define NH 256
#define NL 20000
#define NU 20000
#define NEL 500000
#define NEU 400000

// ---------------- scratch (floats) ------------------------------------------
#define OFF_ENCW 0ull
#define OFF_EWU  (OFF_ENCW + (size_t)NL * NH)
#define OFF_XEH  (OFF_EWU  + (size_t)NU * NH)
#define OFF_XEM  (OFF_XEH  + (size_t)NB * NS * NH / 2)
#define OFF_XP   (OFF_XEM  + (size_t)NB * NS * NH / 2)
#define OFF_W1H  (OFF_XP   + (size_t)NB * NS * NH)
#define OFF_W1M  (OFF_W1H  + (size_t)NL * 3 * NH / 2)
#define OFF_WIHH (OFF_W1M  + (size_t)NL * 3 * NH / 2)
#define OFF_WIHM (OFF_WIHH + (size_t)NH * NH / 2)
#define OFF_FEAT (OFF_WIHM + (size_t)NH * NH / 2)
#define OFF_FH   (OFF_FEAT + (size_t)NB * 3 * NH)
#define OFF_FM   (OFF_FH   + (size_t)NB * 3 * NH / 2)
#define OFF_HA   (OFF_FM   + (size_t)NB * 3 * NH / 2)
#define OFF_HB   (OFF_HA   + (size_t)NB * NH)
#define OFF_SIM  (OFF_HB   + (size_t)NB * NH)
#define OFF_WN   (OFF_SIM  + (size_t)NB * NS)
#define OFF_NEED (OFF_WN   + (size_t)NB * NS)
#define SCRATCH_FLOATS (OFF_NEED + (size_t)NU)

__device__ __align__(16) float g_scratch[SCRATCH_FLOATS];

// ---------------- PTX helpers -----------------------------------------------
__device__ __forceinline__ uint32_t smem_u32(const void* p) {
    uint32_t a;
    asm("{ .reg .u64 t; cvta.to.shared.u64 t, %1; cvt.u32.u64 %0, t; }" : "=r"(a) : "l"(p));
    return a;
}
#define SWZ128(o) ((o) ^ (((o) >> 3) & 0x70))

#define LDSM4(r, a) \
    asm volatile("ldmatrix.sync.aligned.m8n8.x4.shared.b16 {%0,%1,%2,%3}, [%4];" \
        : "=r"((r)[0]), "=r"((r)[1]), "=r"((r)[2]), "=r"((r)[3]) : "r"(a))

#define MMA_BF16(d, a, b) \
    asm volatile("mma.sync.aligned.m16n8k16.row.col.f32.bf16.bf16.f32 " \
        "{%0,%1,%2,%3}, {%4,%5,%6,%7}, {%8,%9}, {%0,%1,%2,%3};" \
        : "+f"((d)[0]), "+f"((d)[1]), "+f"((d)[2]), "+f"((d)[3]) \
        : "r"((a)[0]), "r"((a)[1]), "r"((a)[2]), "r"((a)[3]), "r"((b)[0]), "r"((b)[1]))

__device__ __forceinline__ void cp16(uint32_t dst, const void* src, bool ok) {
    asm volatile("cp.async.cg.shared.global [%0], [%1], 16, %2;"
                 :: "r"(dst), "l"(src), "r"(ok ? 16 : 0) : "memory");
}
__device__ __forceinline__ void cp_commit() { asm volatile("cp.async.commit_group;" ::: "memory"); }
__device__ __forceinline__ void cp_wait1()  { asm volatile("cp.async.wait_group 1;" ::: "memory"); }
__device__ __forceinline__ void cp_wait0()  { asm volatile("cp.async.wait_group 0;" ::: "memory"); }

// ---------------- small kernels ---------------------------------------------
__global__ void zero_k(float* __restrict__ p, int n) {
    int i = blockIdx.x * blockDim.x + threadIdx.x;
    if (i < n) p[i] = 0.0f;
}
__global__ void copy_k(float* __restrict__ dst, const float* __restrict__ src, int n) {
    int i = blockIdx.x * blockDim.x + threadIdx.x;
    if (i < n) dst[i] = src[i];
}
__global__ void mark_k(const int* __restrict__ uid, int* __restrict__ needed) {
    int i = blockIdx.x * blockDim.x + threadIdx.x;
    if (i < NB) needed[uid[i]] = 1;
}
__global__ void split_k(const float* __restrict__ src, __nv_bfloat16* __restrict__ hi,
                        __nv_bfloat16* __restrict__ mi, int n) {
    int i = blockIdx.x * blockDim.x + threadIdx.x;
    if (i < n) {
        float x = src[i];
        __nv_bfloat16 h = __float2bfloat16(x);
        hi[i] = h;
        mi[i] = __float2bfloat16(x - __bfloat162float(h));
    }
}

// ---------------- segment-sum scatters (vector red) -------------------------
__global__ void scatter_loc_k(const int* __restrict__ row, const int* __restrict__ col,
                              const float* __restrict__ vals, const float* __restrict__ emb,
                              float* __restrict__ out) {
    int t = blockIdx.x * blockDim.x + threadIdx.x;
    int e = t >> 6;
    if (e >= NEL) return;
    int q = (t & 63) << 2;
    int r = row[e], cl = col[e];
    float v = vals[e];
    float4 x = *(const float4*)(emb + (size_t)cl * NH + q);
    float* dst = out + (size_t)r * NH + q;
    asm volatile("red.global.add.v4.f32 [%0], {%1, %2, %3, %4};"
                 :: "l"(dst), "f"(v * x.x), "f"(v * x.y), "f"(v * x.z), "f"(v * x.w) : "memory");
}
__global__ void scatter_usr_k(const int* __restrict__ row, const int* __restrict__ col,
                              const float* __restrict__ vals, const float* __restrict__ emb,
                              float* __restrict__ out, const int* __restrict__ needed) {
    int t = blockIdx.x * blockDim.x + threadIdx.x;
    int e = t >> 6;
    if (e >= NEU) return;
    int r = row[e];
    if (!needed[r]) return;
    int q = (t & 63) << 2;
    int cl = col[e];
    float v = vals[e];
    float4 x = *(const float4*)(emb + (size_t)cl * NH + q);
    float* dst = out + (size_t)r * NH + q;
    asm volatile("red.global.add.v4.f32 [%0], {%1, %2, %3, %4};"
                 :: "l"(dst), "f"(v * x.x), "f"(v * x.y), "f"(v * x.z), "f"(v * x.w) : "memory");
}

// ---------------- gather x_emb (bf16 splits) + similarity -------------------
__global__ void gather_sim_k(const int* __restrict__ fsm, const int* __restrict__ uid,
                             const float* __restrict__ encw, const float* __restrict__ ewu,
                             __nv_bfloat16* __restrict__ xeh, __nv_bfloat16* __restrict__ xem,
                             float* __restrict__ sim) {
    int pair = blockIdx.x;
    int h = threadIdx.x;
    int b = pair / NS;
    int loc = fsm[pair];
    float x = encw[(size_t)loc * NH + h];
    __nv_bfloat16 xh = __float2bfloat16(x);
    xeh[(size_t)pair * NH + h] = xh;
    xem[(size_t)pair * NH + h] = __float2bfloat16(x - __bfloat162float(xh));
    float u = ewu[(size_t)uid[b] * NH + h];
    float d = u - x;
    __shared__ float red[NH];
    red[h] = d * d;
    __syncthreads();
    for (int o = NH / 2; o > 0; o >>= 1) {
        if (h < o) red[h] += red[h + o];
        __syncthreads();
    }
    if (h == 0) sim[pair] = expf(-sqrtf(red[0]));
}

// ---------------- decay weights ---------------------------------------------
__global__ void weights_k(const float* __restrict__ td, const float* __restrict__ gd,
                          const float* __restrict__ sim, const int* __restrict__ length,
                          float* __restrict__ wn) {
    int b = blockIdx.x;
    int s = threadIdx.x;
    __shared__ float red[128];
    float w = 0.0f;
    if (s < NS) {
        float t = td[b * NS + s];
        float a = (cosf(t * (6.2831853071795864769f / 86400.0f)) + 1.0f) * 0.5f
                  * expf(-t * (0.1f / 86400.0f));
        float bb = expf(-gd[b * NS + s] * 1000.0f);
        w = (a * bb + 1e-10f) * sim[b * NS + s];
        if (s >= length[b]) w = 0.0f;
    }
    red[s] = w;
    __syncthreads();
    for (int o = 64; o > 0; o >>= 1) {
        if (s < o) red[s] += red[s + o];
        __syncthreads();
    }
    float denom = red[0];
    if (s < NS) wn[b * NS + s] = w / denom;
}

// ---------------- mma.sync bf16x3 GEMM: C[M,N]=A@B^T + bias -----------------
// Block 128x128, BK=64 (128B SW128 rows), 8 warps @ 64x32, double-buffered.
#define STG_B 65536                      // 4 arrays * 128 rows * 128B
#define SMEM_GEMM (2 * STG_B)

__global__ __launch_bounds__(256, 1)
void gemm3(const __nv_bfloat16* __restrict__ Ah, const __nv_bfloat16* __restrict__ Am,
           const __nv_bfloat16* __restrict__ Bh, const __nv_bfloat16* __restrict__ Bm,
           int Nlog, int K, float* __restrict__ C, const float* __restrict__ bias) {
    extern __shared__ char smem[];
    uint32_t sb = smem_u32(smem);
    int tid = threadIdx.x;
    int lane = tid & 31;
    int wid = tid >> 5;
    int wm = wid >> 2, wn = wid & 3;      // warp grid 2(m) x 4(n)
    int m0 = blockIdx.x * 128;
    int n0 = blockIdx.y * 128;
    int nc = K >> 6;

    const __nv_bfloat16* bases[4] = {Ah, Am, Bh, Bm};
    auto load_chunk = [&](int stage, int c) {
#pragma unroll
        for (int i = 0; i < 16; i++) {
            int seg = tid + i * 256;
            int arr = seg >> 10;           // 0:Ah 1:Am 2:Bh 3:Bm
            int rem = seg & 1023;
            int row = rem >> 3;
            int c16 = rem & 7;
            uint32_t dst = sb + stage * STG_B + arr * 16384 + SWZ128(row * 128 + c16 * 16);
            int rg = (arr < 2) ? (m0 + row) : (n0 + row);
            bool ok = (arr < 2) || (rg < Nlog);
            cp16(dst, bases[arr] + (size_t)rg * K + c * 64 + c16 * 8, ok);
        }
        cp_commit();
    };

    float acc[4][4][4];
#pragma unroll
    for (int a = 0; a < 4; a++)
#pragma unroll
        for (int b = 0; b < 4; b++)
#pragma unroll
            for (int d = 0; d < 4; d++) acc[a][b][d] = 0.0f;

    int lrow = lane & 15;                 // ldmatrix row-within-16
    int lchunk = lane >> 4;               // 0/1: k 16B chunk select

    load_chunk(0, 0);
    for (int c = 0; c < nc; c++) {
        if (c + 1 < nc) { load_chunk((c + 1) & 1, c + 1); cp_wait1(); }
        else cp_wait0();
        __syncthreads();
        uint32_t stg = sb + (c & 1) * STG_B;
#pragma unroll
        for (int s = 0; s < 4; s++) {     // 4 k16 steps per BK=64
            uint32_t ah[4][4], am[4][4];
#pragma unroll
            for (int mt = 0; mt < 4; mt++) {
                int r = wm * 64 + mt * 16 + lrow;
                uint32_t off = SWZ128(r * 128 + (s * 2 + lchunk) * 16);
                LDSM4(ah[mt], stg + off);
                LDSM4(am[mt], stg + 16384 + off);
            }
            uint32_t bh[4][2], bm[4][2];
#pragma unroll
            for (int g = 0; g < 2; g++) {
                int r = wn * 32 + g * 16 + lrow;
                uint32_t off = SWZ128(r * 128 + (s * 2 + lchunk) * 16);
                uint32_t q[4];
                LDSM4(q, stg + 32768 + off);
                bh[2 * g][0] = q[0]; bh[2 * g + 1][0] = q[1];
                bh[2 * g][1] = q[2]; bh[2 * g + 1][1] = q[3];
                LDSM4(q, stg + 49152 + off);
                bm[2 * g][0] = q[0]; bm[2 * g + 1][0] = q[1];
                bm[2 * g][1] = q[2]; bm[2 * g + 1][1] = q[3];
            }
#pragma unroll
            for (int mt = 0; mt < 4; mt++)
#pragma unroll
                for (int nt = 0; nt < 4; nt++) {
                    MMA_BF16(acc[mt][nt], ah[mt], bh[nt]);
                    MMA_BF16(acc[mt][nt], ah[mt], bm[nt]);
                    MMA_BF16(acc[mt][nt], am[mt], bh[nt]);
                }
        }
        __syncthreads();
    }

    // epilogue: d0,d1 -> (row, n..n+1); d2,d3 -> (row+8, n..n+1)
#pragma unroll
    for (int mt = 0; mt < 4; mt++) {
        int r0 = m0 + wm * 64 + mt * 16 + (lane >> 2);
#pragma unroll
        for (int nt = 0; nt < 4; nt++) {
            int nn = n0 + wn * 32 + nt * 8 + (lane & 3) * 2;
            if (nn < Nlog) {
                float b0 = bias[nn], b1 = bias[nn + 1];
                float2 v0 = make_float2(acc[mt][nt][0] + b0, acc[mt][nt][1] + b1);
                *(float2*)(C + (size_t)r0 * Nlog + nn) = v0;
                float2 v1 = make_float2(acc[mt][nt][2] + b0, acc[mt][nt][3] + b1);
                *(float2*)(C + (size_t)(r0 + 8) * Nlog + nn) = v1;
            }
        }
    }
}

// ---------------- SIMT RNN step GEMM (64x64 tile) ---------------------------
__global__ __launch_bounds__(256)
void rnn_step(const float* __restrict__ A, const float* __restrict__ Bm,
              float* __restrict__ C, const float* __restrict__ bias,
              const float* __restrict__ xp, const float* __restrict__ wn,
              float* __restrict__ feat, int s) {
    const int BK = 16;
    __shared__ __align__(16) float As[BK][64];
    __shared__ __align__(16) float Bs[BK][64];
    int tid = threadIdx.x;
    int m0 = blockIdx.y * 64, n0 = blockIdx.x * 64;
    int lr = tid >> 2, lc = (tid & 3) << 2;
    int ty = tid >> 4, tx = tid & 15;
    float acc[4][4] = {};
    for (int k0 = 0; k0 < NH; k0 += BK) {
        float4 av = *(const float4*)(A + (size_t)(m0 + lr) * NH + k0 + lc);
        As[lc + 0][lr] = av.x; As[lc + 1][lr] = av.y;
        As[lc + 2][lr] = av.z; As[lc + 3][lr] = av.w;
        float4 bv = *(const float4*)(Bm + (size_t)(n0 + lr) * NH + k0 + lc);
        Bs[lc + 0][lr] = bv.x; Bs[lc + 1][lr] = bv.y;
        Bs[lc + 2][lr] = bv.z; Bs[lc + 3][lr] = bv.w;
        __syncthreads();
#pragma unroll
        for (int kk = 0; kk < BK; kk++) {
            float4 a4 = *(const float4*)&As[kk][ty * 4];
            float4 b4 = *(const float4*)&Bs[kk][tx * 4];
            float ar[4] = {a4.x, a4.y, a4.z, a4.w};
            float br[4] = {b4.x, b4.y, b4.z, b4.w};
#pragma unroll
            for (int i = 0; i < 4; i++)
#pragma unroll
                for (int j = 0; j < 4; j++) acc[i][j] += ar[i] * br[j];
        }
        __syncthreads();
    }
#pragma unroll
    for (int i = 0; i < 4; i++) {
        int m = m0 + ty * 4 + i;
#pragma unroll
        for (int j = 0; j < 4; j++) {
            int n = n0 + tx * 4 + j;
            float v = acc[i][j] + xp[((size_t)m * NS + s) * NH + n] + bias[n];
            v = tanhf(v);
            C[(size_t)m * NH + n] = v;
            feat[(size_t)m * 3 * NH + n] += v * wn[m * NS + s];
        }
    }
}

// ---------------- out_w2 / p_u ----------------------------------------------
__global__ void outw2_k(const int* __restrict__ fseq, const float* __restrict__ emb2,
                        const float* __restrict__ wn, float* __restrict__ feat) {
    int b = blockIdx.x;
    int h = threadIdx.x;
    float acc = 0.0f;
    for (int s = 0; s < NS; s++) {
        int loc = fseq[b * NS + s];
        acc += emb2[(size_t)loc * NH + h] * wn[b * NS + s];
    }
    feat[(size_t)b * 3 * NH + 2 * NH + h] = acc;
}
__global__ void pu_k(const int* __restrict__ uid, const float* __restrict__ user_emb,
                     float* __restrict__ feat) {
    int b = blockIdx.x;
    int h = threadIdx.x;
    feat[(size_t)b * 3 * NH + NH + h] = user_emb[(size_t)uid[b] * NH + h];
}

// ---------------- host launcher ---------------------------------------------
extern "C" void kernel_launch(void* const* d_in, const int* in_sizes, int n_in,
                              void* d_out, int out_size) {
    const int*   full_seq     = (const int*)d_in[0];
    const int*   full_seq_map = (const int*)d_in[1];
    const int*   length       = (const int*)d_in[2];
    const int*   user_id      = (const int*)d_in[3];
    const float* time_delta   = (const float*)d_in[4];
    const float* geo_delta    = (const float*)d_in[5];
    const float* enc_emb      = (const float*)d_in[6];
    const float* user_emb     = (const float*)d_in[7];
    const float* emb2         = (const float*)d_in[8];
    const int*   row_loc      = (const int*)d_in[9];
    const int*   col_loc      = (const int*)d_in[10];
    const float* vals_loc     = (const float*)d_in[11];
    const int*   row_usr      = (const int*)d_in[12];
    const int*   col_usr      = (const int*)d_in[13];
    const float* vals_usr     = (const float*)d_in[14];
    const float* W_ih         = (const float*)d_in[15];
    const float* W_hh         = (const float*)d_in[16];
    const float* b_ih         = (const float*)d_in[17];
    const float* b_hh         = (const float*)d_in[18];
    const float* W1           = (const float*)d_in[19];
    const float* b1           = (const float*)d_in[20];
    const float* h0           = (const float*)d_in[21];
    float* out = (float*)d_out;

    float* base = nullptr;
    cudaGetSymbolAddress((void**)&base, g_scratch);
    float* encw = base + OFF_ENCW;
    float* ewu  = base + OFF_EWU;
    __nv_bfloat16* xeh = (__nv_bfloat16*)(base + OFF_XEH);
    __nv_bfloat16* xem = (__nv_bfloat16*)(base + OFF_XEM);
    float* xp   = base + OFF_XP;
    __nv_bfloat16* w1h = (__nv_bfloat16*)(base + OFF_W1H);
    __nv_bfloat16* w1m = (__nv_bfloat16*)(base + OFF_W1M);
    __nv_bfloat16* wih = (__nv_bfloat16*)(base + OFF_WIHH);
    __nv_bfloat16* wim = (__nv_bfloat16*)(base + OFF_WIHM);
    float* feat = base + OFF_FEAT;
    __nv_bfloat16* fh = (__nv_bfloat16*)(base + OFF_FH);
    __nv_bfloat16* fm = (__nv_bfloat16*)(base + OFF_FM);
    float* ha   = base + OFF_HA;
    float* hb   = base + OFF_HB;
    float* sim  = base + OFF_SIM;
    float* wn   = base + OFF_WN;
    int*   needed = (int*)(base + OFF_NEED);

    cudaFuncSetAttribute(gemm3, cudaFuncAttributeMaxDynamicSharedMemorySize, SMEM_GEMM);

    {
        int n = (int)(2 * (size_t)NL * NH);
        zero_k<<<(n + 255) / 256, 256>>>(encw, n);
    }
    zero_k<<<(NB * 3 * NH + 255) / 256, 256>>>(feat, NB * 3 * NH);
    zero_k<<<(NU + 255) / 256, 256>>>((float*)needed, NU);
    mark_k<<<(NB + 255) / 256, 256>>>(user_id, needed);

    scatter_loc_k<<<(NEL * 64 + 255) / 256, 256>>>(row_loc, col_loc, vals_loc, enc_emb, encw);
    scatter_usr_k<<<(NEU * 64 + 255) / 256, 256>>>(row_usr, col_usr, vals_usr, enc_emb, ewu, needed);

    gather_sim_k<<<NB * NS, NH>>>(full_seq_map, user_id, encw, ewu, xeh, xem, sim);
    weights_k<<<NB, 128>>>(time_delta, geo_delta, sim, length, wn);

    split_k<<<(NH * NH + 255) / 256, 256>>>(W_ih, wih, wim, NH * NH);
    split_k<<<(NL * 3 * NH + 255) / 256, 256>>>(W1, w1h, w1m, NL * 3 * NH);

    // XP = x_emb @ W_ih^T + b_ih   (mma.sync, M=102400, N=256, K=256)
    gemm3<<<dim3((NB * NS) / 128, 2), 256, SMEM_GEMM>>>(xeh, xem, wih, wim, NH, NH, xp, b_ih);

    // RNN: 100 SIMT steps
    copy_k<<<(NB * NH + 255) / 256, 256>>>(ha, h0, NB * NH);
    float* hc = ha;
    float* hn = hb;
    for (int s = 0; s < NS; s++) {
        rnn_step<<<dim3(NH / 64, NB / 64), 256>>>(hc, W_hh, hn, b_hh, xp, wn, feat, s);
        float* t = hc; hc = hn; hn = t;
    }

    outw2_k<<<NB, NH>>>(full_seq, emb2, wn, feat);
    pu_k<<<NB, NH>>>(user_id, user_emb, feat);

    // final: out = feat @ W1^T + b1  (mma.sync, M=1024, N=20000, K=768)
    split_k<<<(NB * 3 * NH + 255) / 256, 256>>>(feat, fh, fm, NB * 3 * NH);
    gemm3<<<dim3(NB / 128, (NL + 127) / 128), 256, SMEM_GEMM>>>(fh, fm, w1h, w1m, NL, 3 * NH, out, b1);
}

// round 6
// speedup vs baseline: 3.5058x; 2.3105x over previous
#include <cuda_runtime.h>
#include <cuda_bf16.h>
#include <math.h>
#include <stdint.h>

#define NB 1024
#define NS 100
#define NH 256
#define NL 20000
#define NU 20000
#define NEL 500000
#define NEU 400000

// ---------------- scratch (float units) --------------------------------------
#define OFF_ENCW 0ull
#define OFF_EWU  (OFF_ENCW + (size_t)NL * NH)
#define OFF_XEH  (OFF_EWU  + (size_t)NU * NH)
#define OFF_XEM  (OFF_XEH  + (size_t)NB * NS * NH / 2)
#define OFF_XP   (OFF_XEM  + (size_t)NB * NS * NH / 2)
#define OFF_W1H  (OFF_XP   + (size_t)NB * NS * NH)
#define OFF_W1M  (OFF_W1H  + (size_t)NL * 3 * NH / 2)
#define OFF_WIHH (OFF_W1M  + (size_t)NL * 3 * NH / 2)
#define OFF_WIHM (OFF_WIHH + (size_t)NH * NH / 2)
#define OFF_WHHH (OFF_WIHM + (size_t)NH * NH / 2)
#define OFF_WHHM (OFF_WHHH + (size_t)NH * NH / 2)
#define OFF_FH   (OFF_WHHM + (size_t)NH * NH / 2)
#define OFF_FM   (OFF_FH   + (size_t)NB * 3 * NH / 2)
#define OFF_SIM  (OFF_FM   + (size_t)NB * 3 * NH / 2)
#define OFF_WN   (OFF_SIM  + (size_t)NB * NS)
#define OFF_NEED (OFF_WN   + (size_t)NB * NS)
#define SCRATCH_FLOATS (OFF_NEED + (size_t)NU)

__device__ __align__(16) float g_scratch[SCRATCH_FLOATS];

// ---------------- PTX helpers -----------------------------------------------
__device__ __forceinline__ uint32_t smem_u32(const void* p) {
    uint32_t a;
    asm("{ .reg .u64 t; cvta.to.shared.u64 t, %1; cvt.u32.u64 %0, t; }" : "=r"(a) : "l"(p));
    return a;
}
#define SWZ128(o) ((o) ^ (((o) >> 3) & 0x70))

#define LDSM4(r, a) \
    asm volatile("ldmatrix.sync.aligned.m8n8.x4.shared.b16 {%0,%1,%2,%3}, [%4];" \
        : "=r"((r)[0]), "=r"((r)[1]), "=r"((r)[2]), "=r"((r)[3]) : "r"(a))

#define MMA_BF16(d, a, b) \
    asm volatile("mma.sync.aligned.m16n8k16.row.col.f32.bf16.bf16.f32 " \
        "{%0,%1,%2,%3}, {%4,%5,%6,%7}, {%8,%9}, {%0,%1,%2,%3};" \
        : "+f"((d)[0]), "+f"((d)[1]), "+f"((d)[2]), "+f"((d)[3]) \
        : "r"((a)[0]), "r"((a)[1]), "r"((a)[2]), "r"((a)[3]), "r"((b)[0]), "r"((b)[1]))

__device__ __forceinline__ void cp16(uint32_t dst, const void* src, bool ok) {
    asm volatile("cp.async.cg.shared.global [%0], [%1], 16, %2;"
                 :: "r"(dst), "l"(src), "r"(ok ? 16 : 0) : "memory");
}
__device__ __forceinline__ void cp_commit() { asm volatile("cp.async.commit_group;" ::: "memory"); }
__device__ __forceinline__ void cp_wait1()  { asm volatile("cp.async.wait_group 1;" ::: "memory"); }
__device__ __forceinline__ void cp_wait0()  { asm volatile("cp.async.wait_group 0;" ::: "memory"); }

// ---------------- small kernels ---------------------------------------------
__global__ void zero_k(float* __restrict__ p, int n) {
    int i = blockIdx.x * blockDim.x + threadIdx.x;
    if (i < n) p[i] = 0.0f;
}
__global__ void mark_k(const int* __restrict__ uid, int* __restrict__ needed) {
    int i = blockIdx.x * blockDim.x + threadIdx.x;
    if (i < NB) needed[uid[i]] = 1;
}
__global__ void split_k(const float* __restrict__ src, __nv_bfloat16* __restrict__ hi,
                        __nv_bfloat16* __restrict__ mi, int n) {
    int i = blockIdx.x * blockDim.x + threadIdx.x;
    if (i < n) {
        float x = src[i];
        __nv_bfloat16 h = __float2bfloat16(x);
        hi[i] = h;
        mi[i] = __float2bfloat16(x - __bfloat162float(h));
    }
}

// ---------------- segment-sum scatters (vector red) -------------------------
__global__ void scatter_loc_k(const int* __restrict__ row, const int* __restrict__ col,
                              const float* __restrict__ vals, const float* __restrict__ emb,
                              float* __restrict__ out) {
    int t = blockIdx.x * blockDim.x + threadIdx.x;
    int e = t >> 6;
    if (e >= NEL) return;
    int q = (t & 63) << 2;
    int r = row[e], cl = col[e];
    float v = vals[e];
    float4 x = *(const float4*)(emb + (size_t)cl * NH + q);
    float* dst = out + (size_t)r * NH + q;
    asm volatile("red.global.add.v4.f32 [%0], {%1, %2, %3, %4};"
                 :: "l"(dst), "f"(v * x.x), "f"(v * x.y), "f"(v * x.z), "f"(v * x.w) : "memory");
}
__global__ void scatter_usr_k(const int* __restrict__ row, const int* __restrict__ col,
                              const float* __restrict__ vals, const float* __restrict__ emb,
                              float* __restrict__ out, const int* __restrict__ needed) {
    int t = blockIdx.x * blockDim.x + threadIdx.x;
    int e = t >> 6;
    if (e >= NEU) return;
    int r = row[e];
    if (!needed[r]) return;
    int q = (t & 63) << 2;
    int cl = col[e];
    float v = vals[e];
    float4 x = *(const float4*)(emb + (size_t)cl * NH + q);
    float* dst = out + (size_t)r * NH + q;
    asm volatile("red.global.add.v4.f32 [%0], {%1, %2, %3, %4};"
                 :: "l"(dst), "f"(v * x.x), "f"(v * x.y), "f"(v * x.z), "f"(v * x.w) : "memory");
}

// ---------------- gather x_emb (bf16 splits) + similarity: warp per pair ----
__global__ void gather_sim_k(const int* __restrict__ fsm, const int* __restrict__ uid,
                             const float* __restrict__ encw, const float* __restrict__ ewu,
                             __nv_bfloat16* __restrict__ xeh, __nv_bfloat16* __restrict__ xem,
                             float* __restrict__ sim) {
    int tid = threadIdx.x;
    int lane = tid & 31;
    int pair = blockIdx.x * 8 + (tid >> 5);
    int b = pair / NS;
    int loc = fsm[pair];
    const float* xr = encw + (size_t)loc * NH + lane * 8;
    const float* ur = ewu + (size_t)uid[b] * NH + lane * 8;
    float ss = 0.0f;
#pragma unroll
    for (int g = 0; g < 2; g++) {
        float4 x = *(const float4*)(xr + g * 4);
        float4 u = *(const float4*)(ur + g * 4);
        float xv[4] = {x.x, x.y, x.z, x.w};
        float uv[4] = {u.x, u.y, u.z, u.w};
#pragma unroll
        for (int j = 0; j < 4; j++) {
            float d = uv[j] - xv[j];
            ss += d * d;
            __nv_bfloat16 hh = __float2bfloat16(xv[j]);
            int cc = lane * 8 + g * 4 + j;
            xeh[(size_t)pair * NH + cc] = hh;
            xem[(size_t)pair * NH + cc] = __float2bfloat16(xv[j] - __bfloat162float(hh));
        }
    }
#pragma unroll
    for (int o = 16; o > 0; o >>= 1) ss += __shfl_xor_sync(0xFFFFFFFFu, ss, o);
    if (lane == 0) sim[pair] = expf(-sqrtf(ss));
}

// ---------------- decay weights ---------------------------------------------
__global__ void weights_k(const float* __restrict__ td, const float* __restrict__ gd,
                          const float* __restrict__ sim, const int* __restrict__ length,
                          float* __restrict__ wn) {
    int b = blockIdx.x;
    int s = threadIdx.x;
    __shared__ float red[128];
    float w = 0.0f;
    if (s < NS) {
        float t = td[b * NS + s];
        float a = (cosf(t * (6.2831853071795864769f / 86400.0f)) + 1.0f) * 0.5f
                  * expf(-t * (0.1f / 86400.0f));
        float bb = expf(-gd[b * NS + s] * 1000.0f);
        w = (a * bb + 1e-10f) * sim[b * NS + s];
        if (s >= length[b]) w = 0.0f;
    }
    red[s] = w;
    __syncthreads();
    for (int o = 64; o > 0; o >>= 1) {
        if (s < o) red[s] += red[s + o];
        __syncthreads();
    }
    float denom = red[0];
    if (s < NS) wn[b * NS + s] = w / denom;
}

// ---------------- mma.sync bf16x3 GEMM: C[M,N]=A@B^T + bias -----------------
#define STG_B 65536
#define SMEM_GEMM (2 * STG_B)

__global__ __launch_bounds__(256, 1)
void gemm3(const __nv_bfloat16* __restrict__ Ah, const __nv_bfloat16* __restrict__ Am,
           const __nv_bfloat16* __restrict__ Bh, const __nv_bfloat16* __restrict__ Bm,
           int Nlog, int K, float* __restrict__ C, const float* __restrict__ bias) {
    extern __shared__ char smem[];
    uint32_t sb = smem_u32(smem);
    int tid = threadIdx.x;
    int lane = tid & 31;
    int wid = tid >> 5;
    int wm = wid >> 2, wn = wid & 3;
    int m0 = blockIdx.x * 128;
    int n0 = blockIdx.y * 128;
    int nc = K >> 6;

    const __nv_bfloat16* bases[4] = {Ah, Am, Bh, Bm};
    auto load_chunk = [&](int stage, int c) {
#pragma unroll
        for (int i = 0; i < 16; i++) {
            int seg = tid + i * 256;
            int arr = seg >> 10;
            int rem = seg & 1023;
            int row = rem >> 3;
            int c16 = rem & 7;
            uint32_t dst = sb + stage * STG_B + arr * 16384 + SWZ128(row * 128 + c16 * 16);
            int rg = (arr < 2) ? (m0 + row) : (n0 + row);
            bool ok = (arr < 2) || (rg < Nlog);
            cp16(dst, bases[arr] + (size_t)rg * K + c * 64 + c16 * 8, ok);
        }
        cp_commit();
    };

    float acc[4][4][4];
#pragma unroll
    for (int a = 0; a < 4; a++)
#pragma unroll
        for (int b = 0; b < 4; b++)
#pragma unroll
            for (int d = 0; d < 4; d++) acc[a][b][d] = 0.0f;

    int lrow = lane & 15;
    int lchunk = lane >> 4;

    load_chunk(0, 0);
    for (int c = 0; c < nc; c++) {
        if (c + 1 < nc) { load_chunk((c + 1) & 1, c + 1); cp_wait1(); }
        else cp_wait0();
        __syncthreads();
        uint32_t stg = sb + (c & 1) * STG_B;
#pragma unroll
        for (int s = 0; s < 4; s++) {
            uint32_t ah[4][4], am[4][4];
#pragma unroll
            for (int mt = 0; mt < 4; mt++) {
                int r = wm * 64 + mt * 16 + lrow;
                uint32_t off = SWZ128(r * 128 + (s * 2 + lchunk) * 16);
                LDSM4(ah[mt], stg + off);
                LDSM4(am[mt], stg + 16384 + off);
            }
            uint32_t bh[4][2], bm[4][2];
#pragma unroll
            for (int g = 0; g < 2; g++) {
                int r = wn * 32 + g * 16 + lrow;
                uint32_t off = SWZ128(r * 128 + (s * 2 + lchunk) * 16);
                uint32_t q[4];
                LDSM4(q, stg + 32768 + off);
                bh[2 * g][0] = q[0]; bh[2 * g + 1][0] = q[1];
                bh[2 * g][1] = q[2]; bh[2 * g + 1][1] = q[3];
                LDSM4(q, stg + 49152 + off);
                bm[2 * g][0] = q[0]; bm[2 * g + 1][0] = q[1];
                bm[2 * g][1] = q[2]; bm[2 * g + 1][1] = q[3];
            }
#pragma unroll
            for (int mt = 0; mt < 4; mt++)
#pragma unroll
                for (int nt = 0; nt < 4; nt++) {
                    MMA_BF16(acc[mt][nt], ah[mt], bh[nt]);
                    MMA_BF16(acc[mt][nt], ah[mt], bm[nt]);
                    MMA_BF16(acc[mt][nt], am[mt], bh[nt]);
                }
        }
        __syncthreads();
    }

#pragma unroll
    for (int mt = 0; mt < 4; mt++) {
        int r0 = m0 + wm * 64 + mt * 16 + (lane >> 2);
#pragma unroll
        for (int nt = 0; nt < 4; nt++) {
            int nn = n0 + wn * 32 + nt * 8 + (lane & 3) * 2;
            if (nn < Nlog) {
                float b0 = bias[nn], b1 = bias[nn + 1];
                float2 v0 = make_float2(acc[mt][nt][0] + b0, acc[mt][nt][1] + b1);
                *(float2*)(C + (size_t)r0 * Nlog + nn) = v0;
                float2 v1 = make_float2(acc[mt][nt][2] + b0, acc[mt][nt][3] + b1);
                *(float2*)(C + (size_t)(r0 + 8) * Nlog + nn) = v1;
            }
        }
    }
}

// ---------------- persistent RNN --------------------------------------------
// 64 CTAs x 16 batch rows. h in smem (bf16 hi/mid, SW128 chunked). Wh resident
// in smem, Wm double-buffer streamed from L2. out_w accumulated in registers,
// written as bf16 hi/mid into fh/fm cols [0, NH).
#define R_AH 0
#define R_AM 8192
#define R_WH 16384
#define R_WM (16384 + 131072)
#define R_WNS (R_WM + 65536)
#define SMEM_RNN (R_WNS + 16 * NS * 4)

__global__ __launch_bounds__(256, 1)
void rnn_persist(const __nv_bfloat16* __restrict__ whh_h, const __nv_bfloat16* __restrict__ whh_m,
                 const float* __restrict__ xp, const float* __restrict__ wn,
                 const float* __restrict__ b_hh, const float* __restrict__ h0,
                 __nv_bfloat16* __restrict__ fh, __nv_bfloat16* __restrict__ fm) {
    extern __shared__ char smem[];
    uint32_t sb = smem_u32(smem);
    int tid = threadIdx.x;
    int lane = tid & 31;
    int wid = tid >> 5;
    int m0 = blockIdx.x * 16;
    float* wns = (float*)(smem + R_WNS);

    // resident Wh load: 4 chunks x 256 rows x 8 c16
#pragma unroll
    for (int i = 0; i < 32; i++) {
        int seg = tid + i * 256;
        int ch = seg >> 11;
        int rem = seg & 2047;
        int row = rem >> 3;
        int c16 = rem & 7;
        cp16(sb + R_WH + ch * 32768 + SWZ128(row * 128 + c16 * 16),
             whh_h + (size_t)row * NH + ch * 64 + c16 * 8, true);
    }
    cp_commit();

    // wn cache + h0 -> A smem (bf16 hi/mid)
    for (int i = tid; i < 16 * NS; i += 256) {
        int r = i / NS, s = i % NS;
        wns[r * NS + s] = wn[(m0 + r) * NS + s];
    }
    for (int i = tid; i < 16 * NH; i += 256) {
        int r = i >> 8, cc = i & 255;
        float x = h0[(size_t)(m0 + r) * NH + cc];
        __nv_bfloat16 hh = __float2bfloat16(x);
        uint32_t off = (cc >> 6) * 2048 + SWZ128(r * 128 + (cc & 63) * 2);
        *(__nv_bfloat16*)(smem + R_AH + off) = hh;
        *(__nv_bfloat16*)(smem + R_AM + off) = __float2bfloat16(x - __bfloat162float(hh));
    }

    // bias fragment
    float bias_r[8];
#pragma unroll
    for (int nt = 0; nt < 4; nt++) {
        int n = wid * 32 + nt * 8 + (lane & 3) * 2;
        bias_r[nt * 2 + 0] = b_hh[n];
        bias_r[nt * 2 + 1] = b_hh[n + 1];
    }

    auto loadWm = [&](int st, int ch) {
#pragma unroll
        for (int i = 0; i < 8; i++) {
            int seg = tid + i * 256;
            int row = seg >> 3;
            int c16 = seg & 7;
            cp16(sb + R_WM + st * 32768 + SWZ128(row * 128 + c16 * 16),
                 whh_m + (size_t)row * NH + ch * 64 + c16 * 8, true);
        }
        cp_commit();
    };

    loadWm(0, 0);
    cp_wait0();
    __syncthreads();

    float acc_out[4][4];
#pragma unroll
    for (int a = 0; a < 4; a++)
#pragma unroll
        for (int d = 0; d < 4; d++) acc_out[a][d] = 0.0f;

    int lrow = lane & 15;
    int lchunk = lane >> 4;
    int r0 = lane >> 2;
    int cg = 0;

    for (int s = 0; s < NS; s++) {
        // prefetch xp fragment for this step
        float2 xpr[4][2];
#pragma unroll
        for (int nt = 0; nt < 4; nt++) {
            int n = wid * 32 + nt * 8 + (lane & 3) * 2;
            xpr[nt][0] = *(const float2*)(xp + ((size_t)(m0 + r0) * NS + s) * NH + n);
            xpr[nt][1] = *(const float2*)(xp + ((size_t)(m0 + r0 + 8) * NS + s) * NH + n);
        }
        float acc[4][4];
#pragma unroll
        for (int a = 0; a < 4; a++)
#pragma unroll
            for (int d = 0; d < 4; d++) acc[a][d] = 0.0f;

        for (int c = 0; c < 4; c++, cg++) {
            int st = cg & 1;
            if (cg + 1 < NS * 4) { loadWm((cg + 1) & 1, (cg + 1) & 3); cp_wait1(); }
            else cp_wait0();
            __syncthreads();
            uint32_t stWh = sb + R_WH + c * 32768;
            uint32_t stWm = sb + R_WM + st * 32768;
#pragma unroll
            for (int s4 = 0; s4 < 4; s4++) {
                uint32_t aoff = c * 2048 + SWZ128(lrow * 128 + (s4 * 2 + lchunk) * 16);
                uint32_t ah[4], am[4];
                LDSM4(ah, sb + R_AH + aoff);
                LDSM4(am, sb + R_AM + aoff);
                uint32_t bh[4][2], bm[4][2];
#pragma unroll
                for (int g = 0; g < 2; g++) {
                    uint32_t off = SWZ128((wid * 32 + g * 16 + lrow) * 128 + (s4 * 2 + lchunk) * 16);
                    uint32_t q[4];
                    LDSM4(q, stWh + off);
                    bh[2 * g][0] = q[0]; bh[2 * g + 1][0] = q[1];
                    bh[2 * g][1] = q[2]; bh[2 * g + 1][1] = q[3];
                    LDSM4(q, stWm + off);
                    bm[2 * g][0] = q[0]; bm[2 * g + 1][0] = q[1];
                    bm[2 * g][1] = q[2]; bm[2 * g + 1][1] = q[3];
                }
#pragma unroll
                for (int nt = 0; nt < 4; nt++) {
                    MMA_BF16(acc[nt], ah, bh[nt]);
                    MMA_BF16(acc[nt], ah, bm[nt]);
                    MMA_BF16(acc[nt], am, bh[nt]);
                }
            }
            __syncthreads();
        }

        // epilogue: tanh + out_w accum + write h back to A smem
        float w0 = wns[r0 * NS + s];
        float w1 = wns[(r0 + 8) * NS + s];
#pragma unroll
        for (int nt = 0; nt < 4; nt++) {
            int n = wid * 32 + nt * 8 + (lane & 3) * 2;
            float v00 = tanhf(acc[nt][0] + xpr[nt][0].x + bias_r[nt * 2 + 0]);
            float v01 = tanhf(acc[nt][1] + xpr[nt][0].y + bias_r[nt * 2 + 1]);
            float v10 = tanhf(acc[nt][2] + xpr[nt][1].x + bias_r[nt * 2 + 0]);
            float v11 = tanhf(acc[nt][3] + xpr[nt][1].y + bias_r[nt * 2 + 1]);
            acc_out[nt][0] += v00 * w0;
            acc_out[nt][1] += v01 * w0;
            acc_out[nt][2] += v10 * w1;
            acc_out[nt][3] += v11 * w1;
            __nv_bfloat16 h00 = __float2bfloat16(v00), h01 = __float2bfloat16(v01);
            __nv_bfloat16 h10 = __float2bfloat16(v10), h11 = __float2bfloat16(v11);
            __nv_bfloat162 p0; p0.x = h00; p0.y = h01;
            __nv_bfloat162 p1; p1.x = h10; p1.y = h11;
            __nv_bfloat162 q0; q0.x = __float2bfloat16(v00 - __bfloat162float(h00));
                               q0.y = __float2bfloat16(v01 - __bfloat162float(h01));
            __nv_bfloat162 q1; q1.x = __float2bfloat16(v10 - __bfloat162float(h10));
                               q1.y = __float2bfloat16(v11 - __bfloat162float(h11));
            uint32_t off0 = (n >> 6) * 2048 + SWZ128(r0 * 128 + (n & 63) * 2);
            uint32_t off1 = (n >> 6) * 2048 + SWZ128((r0 + 8) * 128 + (n & 63) * 2);
            *(__nv_bfloat162*)(smem + R_AH + off0) = p0;
            *(__nv_bfloat162*)(smem + R_AH + off1) = p1;
            *(__nv_bfloat162*)(smem + R_AM + off0) = q0;
            *(__nv_bfloat162*)(smem + R_AM + off1) = q1;
        }
        __syncthreads();
    }

    // write out_w into fh/fm cols [0, NH)
#pragma unroll
    for (int nt = 0; nt < 4; nt++) {
        int n = wid * 32 + nt * 8 + (lane & 3) * 2;
#pragma unroll
        for (int rr = 0; rr < 2; rr++) {
            int m = m0 + r0 + rr * 8;
            float v0 = acc_out[nt][rr * 2 + 0];
            float v1 = acc_out[nt][rr * 2 + 1];
            __nv_bfloat16 h0b = __float2bfloat16(v0), h1b = __float2bfloat16(v1);
            fh[(size_t)m * 3 * NH + n] = h0b;
            fh[(size_t)m * 3 * NH + n + 1] = h1b;
            fm[(size_t)m * 3 * NH + n] = __float2bfloat16(v0 - __bfloat162float(h0b));
            fm[(size_t)m * 3 * NH + n + 1] = __float2bfloat16(v1 - __bfloat162float(h1b));
        }
    }
}

// ---------------- out_w2 / p_u (write bf16 splits into feat) ----------------
__global__ void outw2_k(const int* __restrict__ fseq, const float* __restrict__ emb2,
                        const float* __restrict__ wn, __nv_bfloat16* __restrict__ fh,
                        __nv_bfloat16* __restrict__ fm) {
    int b = blockIdx.x;
    int h = threadIdx.x;
    float acc = 0.0f;
    for (int s = 0; s < NS; s++) {
        int loc = fseq[b * NS + s];
        acc += emb2[(size_t)loc * NH + h] * wn[b * NS + s];
    }
    __nv_bfloat16 hh = __float2bfloat16(acc);
    fh[(size_t)b * 3 * NH + 2 * NH + h] = hh;
    fm[(size_t)b * 3 * NH + 2 * NH + h] = __float2bfloat16(acc - __bfloat162float(hh));
}
__global__ void pu_k(const int* __restrict__ uid, const float* __restrict__ user_emb,
                     __nv_bfloat16* __restrict__ fh, __nv_bfloat16* __restrict__ fm) {
    int b = blockIdx.x;
    int h = threadIdx.x;
    float x = user_emb[(size_t)uid[b] * NH + h];
    __nv_bfloat16 hh = __float2bfloat16(x);
    fh[(size_t)b * 3 * NH + NH + h] = hh;
    fm[(size_t)b * 3 * NH + NH + h] = __float2bfloat16(x - __bfloat162float(hh));
}

// ---------------- host launcher ---------------------------------------------
extern "C" void kernel_launch(void* const* d_in, const int* in_sizes, int n_in,
                              void* d_out, int out_size) {
    const int*   full_seq     = (const int*)d_in[0];
    const int*   full_seq_map = (const int*)d_in[1];
    const int*   length       = (const int*)d_in[2];
    const int*   user_id      = (const int*)d_in[3];
    const float* time_delta   = (const float*)d_in[4];
    const float* geo_delta    = (const float*)d_in[5];
    const float* enc_emb      = (const float*)d_in[6];
    const float* user_emb     = (const float*)d_in[7];
    const float* emb2         = (const float*)d_in[8];
    const int*   row_loc      = (const int*)d_in[9];
    const int*   col_loc      = (const int*)d_in[10];
    const float* vals_loc     = (const float*)d_in[11];
    const int*   row_usr      = (const int*)d_in[12];
    const int*   col_usr      = (const int*)d_in[13];
    const float* vals_usr     = (const float*)d_in[14];
    const float* W_ih         = (const float*)d_in[15];
    const float* W_hh         = (const float*)d_in[16];
    const float* b_ih         = (const float*)d_in[17];
    const float* b_hh         = (const float*)d_in[18];
    const float* W1           = (const float*)d_in[19];
    const float* b1           = (const float*)d_in[20];
    const float* h0           = (const float*)d_in[21];
    float* out = (float*)d_out;

    float* base = nullptr;
    cudaGetSymbolAddress((void**)&base, g_scratch);
    float* encw = base + OFF_ENCW;
    float* ewu  = base + OFF_EWU;
    __nv_bfloat16* xeh = (__nv_bfloat16*)(base + OFF_XEH);
    __nv_bfloat16* xem = (__nv_bfloat16*)(base + OFF_XEM);
    float* xp   = base + OFF_XP;
    __nv_bfloat16* w1h = (__nv_bfloat16*)(base + OFF_W1H);
    __nv_bfloat16* w1m = (__nv_bfloat16*)(base + OFF_W1M);
    __nv_bfloat16* wih = (__nv_bfloat16*)(base + OFF_WIHH);
    __nv_bfloat16* wim = (__nv_bfloat16*)(base + OFF_WIHM);
    __nv_bfloat16* whh = (__nv_bfloat16*)(base + OFF_WHHH);
    __nv_bfloat16* whm = (__nv_bfloat16*)(base + OFF_WHHM);
    __nv_bfloat16* fh  = (__nv_bfloat16*)(base + OFF_FH);
    __nv_bfloat16* fm  = (__nv_bfloat16*)(base + OFF_FM);
    float* sim  = base + OFF_SIM;
    float* wn   = base + OFF_WN;
    int*   needed = (int*)(base + OFF_NEED);

    cudaFuncSetAttribute(gemm3, cudaFuncAttributeMaxDynamicSharedMemorySize, SMEM_GEMM);
    cudaFuncSetAttribute(rnn_persist, cudaFuncAttributeMaxDynamicSharedMemorySize, SMEM_RNN);

    {
        int n = (int)(2 * (size_t)NL * NH);
        zero_k<<<(n + 255) / 256, 256>>>(encw, n);
    }
    zero_k<<<(NU + 255) / 256, 256>>>((float*)needed, NU);
    mark_k<<<(NB + 255) / 256, 256>>>(user_id, needed);

    scatter_loc_k<<<(NEL * 64 + 255) / 256, 256>>>(row_loc, col_loc, vals_loc, enc_emb, encw);
    scatter_usr_k<<<(NEU * 64 + 255) / 256, 256>>>(row_usr, col_usr, vals_usr, enc_emb, ewu, needed);

    gather_sim_k<<<NB * NS / 8, 256>>>(full_seq_map, user_id, encw, ewu, xeh, xem, sim);
    weights_k<<<NB, 128>>>(time_delta, geo_delta, sim, length, wn);

    split_k<<<(NH * NH + 255) / 256, 256>>>(W_ih, wih, wim, NH * NH);
    split_k<<<(NH * NH + 255) / 256, 256>>>(W_hh, whh, whm, NH * NH);
    split_k<<<(NL * 3 * NH + 255) / 256, 256>>>(W1, w1h, w1m, NL * 3 * NH);

    // XP = x_emb @ W_ih^T + b_ih
    gemm3<<<dim3((NB * NS) / 128, 2), 256, SMEM_GEMM>>>(xeh, xem, wih, wim, NH, NH, xp, b_ih);

    // feat side blocks
    outw2_k<<<NB, NH>>>(full_seq, emb2, wn, fh, fm);
    pu_k<<<NB, NH>>>(user_id, user_emb, fh, fm);

    // persistent RNN (fills feat cols [0, NH))
    rnn_persist<<<NB / 16, 256, SMEM_RNN>>>(whh, whm, xp, wn, b_hh, h0, fh, fm);

    // final: out = feat @ W1^T + b1
    gemm3<<<dim3(NB / 128, (NL + 127) / 128), 256, SMEM_GEMM>>>(fh, fm, w1h, w1m, NL, 3 * NH, out, b1);
}

// round 7
// speedup vs baseline: 3.5295x; 1.0068x over previous
#include <cuda_runtime.h>
#include <cuda_bf16.h>
#include <math.h>
#include <stdint.h>

#define NB 1024
#define NS 100
#define NH 256
#define NL 20000
#define NU 20000
#define NEL 500000
#define NEU 400000

// ---------------- scratch (float units) --------------------------------------
#define OFF_ENCW 0ull
#define OFF_EWU  (OFF_ENCW + (size_t)NL * NH)
#define OFF_XEH  (OFF_EWU  + (size_t)NU * NH)
#define OFF_XEM  (OFF_XEH  + (size_t)NB * NS * NH / 2)
#define OFF_XP   (OFF_XEM  + (size_t)NB * NS * NH / 2)
#define OFF_W1H  (OFF_XP   + (size_t)NB * NS * NH)
#define OFF_W1M  (OFF_W1H  + (size_t)NL * 3 * NH / 2)
#define OFF_WIHH (OFF_W1M  + (size_t)NL * 3 * NH / 2)
#define OFF_WIHM (OFF_WIHH + (size_t)NH * NH / 2)
#define OFF_WHHH (OFF_WIHM + (size_t)NH * NH / 2)
#define OFF_WHHM (OFF_WHHH + (size_t)NH * NH / 2)
#define OFF_FH   (OFF_WHHM + (size_t)NH * NH / 2)
#define OFF_FM   (OFF_FH   + (size_t)NB * 3 * NH / 2)
#define OFF_SIM  (OFF_FM   + (size_t)NB * 3 * NH / 2)
#define OFF_WN   (OFF_SIM  + (size_t)NB * NS)
#define OFF_NEED (OFF_WN   + (size_t)NB * NS)
#define SCRATCH_FLOATS (OFF_NEED + (size_t)NU)

__device__ __align__(16) float g_scratch[SCRATCH_FLOATS];

// ---------------- PTX helpers -----------------------------------------------
__device__ __forceinline__ uint32_t smem_u32(const void* p) {
    uint32_t a;
    asm("{ .reg .u64 t; cvta.to.shared.u64 t, %1; cvt.u32.u64 %0, t; }" : "=r"(a) : "l"(p));
    return a;
}
#define SWZ128(o) ((o) ^ (((o) >> 3) & 0x70))

#define LDSM4(r, a) \
    asm volatile("ldmatrix.sync.aligned.m8n8.x4.shared.b16 {%0,%1,%2,%3}, [%4];" \
        : "=r"((r)[0]), "=r"((r)[1]), "=r"((r)[2]), "=r"((r)[3]) : "r"(a))

#define MMA_BF16(d, a, b) \
    asm volatile("mma.sync.aligned.m16n8k16.row.col.f32.bf16.bf16.f32 " \
        "{%0,%1,%2,%3}, {%4,%5,%6,%7}, {%8,%9}, {%0,%1,%2,%3};" \
        : "+f"((d)[0]), "+f"((d)[1]), "+f"((d)[2]), "+f"((d)[3]) \
        : "r"((a)[0]), "r"((a)[1]), "r"((a)[2]), "r"((a)[3]), "r"((b)[0]), "r"((b)[1]))

__device__ __forceinline__ void cp16(uint32_t dst, const void* src, bool ok) {
    asm volatile("cp.async.cg.shared.global [%0], [%1], 16, %2;"
                 :: "r"(dst), "l"(src), "r"(ok ? 16 : 0) : "memory");
}
__device__ __forceinline__ void cp_commit() { asm volatile("cp.async.commit_group;" ::: "memory"); }
__device__ __forceinline__ void cp_wait2()  { asm volatile("cp.async.wait_group 2;" ::: "memory"); }
__device__ __forceinline__ void cp_wait1()  { asm volatile("cp.async.wait_group 1;" ::: "memory"); }
__device__ __forceinline__ void cp_wait0()  { asm volatile("cp.async.wait_group 0;" ::: "memory"); }

// ---------------- fused small kernels ----------------------------------------
__global__ void zero_all_k(float* __restrict__ p1, int n1, float* __restrict__ p2, int n2) {
    int i = blockIdx.x * blockDim.x + threadIdx.x;
    if (i < n1) p1[i] = 0.0f;
    else if (i < n1 + n2) p2[i - n1] = 0.0f;
}
__global__ void mark_k(const int* __restrict__ uid, int* __restrict__ needed) {
    int i = blockIdx.x * blockDim.x + threadIdx.x;
    if (i < NB) needed[uid[i]] = 1;
}
// split three fp32 arrays into bf16 hi/mid in one launch
__global__ void split3_k(const float* __restrict__ a, const float* __restrict__ b,
                         const float* __restrict__ c,
                         __nv_bfloat16* __restrict__ ah, __nv_bfloat16* __restrict__ am,
                         __nv_bfloat16* __restrict__ bh, __nv_bfloat16* __restrict__ bm,
                         __nv_bfloat16* __restrict__ ch, __nv_bfloat16* __restrict__ cm) {
    int i = blockIdx.x * blockDim.x + threadIdx.x;
    const int NA = NH * NH, NBB = NH * NH, NC = NL * 3 * NH;
    const float* src;
    __nv_bfloat16 *hi, *mi;
    int j;
    if (i < NA) { src = a; hi = ah; mi = am; j = i; }
    else if (i < NA + NBB) { src = b; hi = bh; mi = bm; j = i - NA; }
    else if (i < NA + NBB + NC) { src = c; hi = ch; mi = cm; j = i - NA - NBB; }
    else return;
    float x = src[j];
    __nv_bfloat16 h = __float2bfloat16(x);
    hi[j] = h;
    mi[j] = __float2bfloat16(x - __bfloat162float(h));
}

// ---------------- segment-sum scatters (vector red) -------------------------
__global__ void scatter_loc_k(const int* __restrict__ row, const int* __restrict__ col,
                              const float* __restrict__ vals, const float* __restrict__ emb,
                              float* __restrict__ out) {
    int t = blockIdx.x * blockDim.x + threadIdx.x;
    int e = t >> 6;
    if (e >= NEL) return;
    int q = (t & 63) << 2;
    int r = row[e], cl = col[e];
    float v = vals[e];
    float4 x = *(const float4*)(emb + (size_t)cl * NH + q);
    float* dst = out + (size_t)r * NH + q;
    asm volatile("red.global.add.v4.f32 [%0], {%1, %2, %3, %4};"
                 :: "l"(dst), "f"(v * x.x), "f"(v * x.y), "f"(v * x.z), "f"(v * x.w) : "memory");
}
__global__ void scatter_usr_k(const int* __restrict__ row, const int* __restrict__ col,
                              const float* __restrict__ vals, const float* __restrict__ emb,
                              float* __restrict__ out, const int* __restrict__ needed) {
    int t = blockIdx.x * blockDim.x + threadIdx.x;
    int e = t >> 6;
    if (e >= NEU) return;
    int r = row[e];
    if (!needed[r]) return;
    int q = (t & 63) << 2;
    int cl = col[e];
    float v = vals[e];
    float4 x = *(const float4*)(emb + (size_t)cl * NH + q);
    float* dst = out + (size_t)r * NH + q;
    asm volatile("red.global.add.v4.f32 [%0], {%1, %2, %3, %4};"
                 :: "l"(dst), "f"(v * x.x), "f"(v * x.y), "f"(v * x.z), "f"(v * x.w) : "memory");
}

// ---------------- gather x_emb (bf16 splits) + similarity: warp per pair ----
__global__ void gather_sim_k(const int* __restrict__ fsm, const int* __restrict__ uid,
                             const float* __restrict__ encw, const float* __restrict__ ewu,
                             __nv_bfloat16* __restrict__ xeh, __nv_bfloat16* __restrict__ xem,
                             float* __restrict__ sim) {
    int tid = threadIdx.x;
    int lane = tid & 31;
    int pair = blockIdx.x * 8 + (tid >> 5);
    int b = pair / NS;
    int loc = fsm[pair];
    const float* xr = encw + (size_t)loc * NH + lane * 8;
    const float* ur = ewu + (size_t)uid[b] * NH + lane * 8;
    float ss = 0.0f;
#pragma unroll
    for (int g = 0; g < 2; g++) {
        float4 x = *(const float4*)(xr + g * 4);
        float4 u = *(const float4*)(ur + g * 4);
        float xv[4] = {x.x, x.y, x.z, x.w};
        float uv[4] = {u.x, u.y, u.z, u.w};
#pragma unroll
        for (int j = 0; j < 4; j++) {
            float d = uv[j] - xv[j];
            ss += d * d;
            __nv_bfloat16 hh = __float2bfloat16(xv[j]);
            int cc = lane * 8 + g * 4 + j;
            xeh[(size_t)pair * NH + cc] = hh;
            xem[(size_t)pair * NH + cc] = __float2bfloat16(xv[j] - __bfloat162float(hh));
        }
    }
#pragma unroll
    for (int o = 16; o > 0; o >>= 1) ss += __shfl_xor_sync(0xFFFFFFFFu, ss, o);
    if (lane == 0) sim[pair] = expf(-sqrtf(ss));
}

// ---------------- decay weights ---------------------------------------------
__global__ void weights_k(const float* __restrict__ td, const float* __restrict__ gd,
                          const float* __restrict__ sim, const int* __restrict__ length,
                          float* __restrict__ wn) {
    int b = blockIdx.x;
    int s = threadIdx.x;
    __shared__ float red[128];
    float w = 0.0f;
    if (s < NS) {
        float t = td[b * NS + s];
        float a = (cosf(t * (6.2831853071795864769f / 86400.0f)) + 1.0f) * 0.5f
                  * expf(-t * (0.1f / 86400.0f));
        float bb = expf(-gd[b * NS + s] * 1000.0f);
        w = (a * bb + 1e-10f) * sim[b * NS + s];
        if (s >= length[b]) w = 0.0f;
    }
    red[s] = w;
    __syncthreads();
    for (int o = 64; o > 0; o >>= 1) {
        if (s < o) red[s] += red[s + o];
        __syncthreads();
    }
    float denom = red[0];
    if (s < NS) wn[b * NS + s] = w / denom;
}

// ---------------- mma.sync bf16x3 GEMM (3-stage pipeline) -------------------
#define STG_B 65536
#define SMEM_GEMM (3 * STG_B)

__global__ __launch_bounds__(256, 1)
void gemm3(const __nv_bfloat16* __restrict__ Ah, const __nv_bfloat16* __restrict__ Am,
           const __nv_bfloat16* __restrict__ Bh, const __nv_bfloat16* __restrict__ Bm,
           int Nlog, int K, float* __restrict__ C, const float* __restrict__ bias) {
    extern __shared__ char smem[];
    uint32_t sb = smem_u32(smem);
    int tid = threadIdx.x;
    int lane = tid & 31;
    int wid = tid >> 5;
    int wm = wid >> 2, wn = wid & 3;
    int m0 = blockIdx.x * 128;
    int n0 = blockIdx.y * 128;
    int nc = K >> 6;

    const __nv_bfloat16* bases[4] = {Ah, Am, Bh, Bm};
    auto load_chunk = [&](int stage, int c) {
#pragma unroll
        for (int i = 0; i < 16; i++) {
            int seg = tid + i * 256;
            int arr = seg >> 10;
            int rem = seg & 1023;
            int row = rem >> 3;
            int c16 = rem & 7;
            uint32_t dst = sb + stage * STG_B + arr * 16384 + SWZ128(row * 128 + c16 * 16);
            int rg = (arr < 2) ? (m0 + row) : (n0 + row);
            bool ok = (arr < 2) || (rg < Nlog);
            cp16(dst, bases[arr] + (size_t)rg * K + c * 64 + c16 * 8, ok);
        }
        cp_commit();
    };

    float acc[4][4][4];
#pragma unroll
    for (int a = 0; a < 4; a++)
#pragma unroll
        for (int b = 0; b < 4; b++)
#pragma unroll
            for (int d = 0; d < 4; d++) acc[a][b][d] = 0.0f;

    int lrow = lane & 15;
    int lchunk = lane >> 4;

    load_chunk(0, 0);
    load_chunk(1, 1);
    for (int c = 0; c < nc; c++) {
        if (c + 2 < nc) { load_chunk((c + 2) % 3, c + 2); cp_wait2(); }
        else if (c + 1 < nc) cp_wait1();
        else cp_wait0();
        __syncthreads();
        uint32_t stg = sb + (c % 3) * STG_B;
#pragma unroll
        for (int s = 0; s < 4; s++) {
            uint32_t ah[4][4], am[4][4];
#pragma unroll
            for (int mt = 0; mt < 4; mt++) {
                int r = wm * 64 + mt * 16 + lrow;
                uint32_t off = SWZ128(r * 128 + (s * 2 + lchunk) * 16);
                LDSM4(ah[mt], stg + off);
                LDSM4(am[mt], stg + 16384 + off);
            }
            uint32_t bh[4][2], bm[4][2];
#pragma unroll
            for (int g = 0; g < 2; g++) {
                int r = wn * 32 + g * 16 + lrow;
                uint32_t off = SWZ128(r * 128 + (s * 2 + lchunk) * 16);
                uint32_t q[4];
                LDSM4(q, stg + 32768 + off);
                bh[2 * g][0] = q[0]; bh[2 * g + 1][0] = q[1];
                bh[2 * g][1] = q[2]; bh[2 * g + 1][1] = q[3];
                LDSM4(q, stg + 49152 + off);
                bm[2 * g][0] = q[0]; bm[2 * g + 1][0] = q[1];
                bm[2 * g][1] = q[2]; bm[2 * g + 1][1] = q[3];
            }
#pragma unroll
            for (int mt = 0; mt < 4; mt++)
#pragma unroll
                for (int nt = 0; nt < 4; nt++) {
                    MMA_BF16(acc[mt][nt], ah[mt], bh[nt]);
                    MMA_BF16(acc[mt][nt], ah[mt], bm[nt]);
                    MMA_BF16(acc[mt][nt], am[mt], bh[nt]);
                }
        }
        __syncthreads();
    }

#pragma unroll
    for (int mt = 0; mt < 4; mt++) {
        int r0 = m0 + wm * 64 + mt * 16 + (lane >> 2);
#pragma unroll
        for (int nt = 0; nt < 4; nt++) {
            int nn = n0 + wn * 32 + nt * 8 + (lane & 3) * 2;
            if (nn < Nlog) {
                float b0 = bias[nn], b1 = bias[nn + 1];
                float2 v0 = make_float2(acc[mt][nt][0] + b0, acc[mt][nt][1] + b1);
                *(float2*)(C + (size_t)r0 * Nlog + nn) = v0;
                float2 v1 = make_float2(acc[mt][nt][2] + b0, acc[mt][nt][3] + b1);
                *(float2*)(C + (size_t)(r0 + 8) * Nlog + nn) = v1;
            }
        }
    }
}

// ---------------- persistent RNN (unchanged from R6) ------------------------
#define R_AH 0
#define R_AM 8192
#define R_WH 16384
#define R_WM (16384 + 131072)
#define R_WNS (R_WM + 65536)
#define SMEM_RNN (R_WNS + 16 * NS * 4)

__global__ __launch_bounds__(256, 1)
void rnn_persist(const __nv_bfloat16* __restrict__ whh_h, const __nv_bfloat16* __restrict__ whh_m,
                 const float* __restrict__ xp, const float* __restrict__ wn,
                 const float* __restrict__ b_hh, const float* __restrict__ h0,
                 __nv_bfloat16* __restrict__ fh, __nv_bfloat16* __restrict__ fm) {
    extern __shared__ char smem[];
    uint32_t sb = smem_u32(smem);
    int tid = threadIdx.x;
    int lane = tid & 31;
    int wid = tid >> 5;
    int m0 = blockIdx.x * 16;
    float* wns = (float*)(smem + R_WNS);

#pragma unroll
    for (int i = 0; i < 32; i++) {
        int seg = tid + i * 256;
        int ch = seg >> 11;
        int rem = seg & 2047;
        int row = rem >> 3;
        int c16 = rem & 7;
        cp16(sb + R_WH + ch * 32768 + SWZ128(row * 128 + c16 * 16),
             whh_h + (size_t)row * NH + ch * 64 + c16 * 8, true);
    }
    cp_commit();

    for (int i = tid; i < 16 * NS; i += 256) {
        int r = i / NS, s = i % NS;
        wns[r * NS + s] = wn[(m0 + r) * NS + s];
    }
    for (int i = tid; i < 16 * NH; i += 256) {
        int r = i >> 8, cc = i & 255;
        float x = h0[(size_t)(m0 + r) * NH + cc];
        __nv_bfloat16 hh = __float2bfloat16(x);
        uint32_t off = (cc >> 6) * 2048 + SWZ128(r * 128 + (cc & 63) * 2);
        *(__nv_bfloat16*)(smem + R_AH + off) = hh;
        *(__nv_bfloat16*)(smem + R_AM + off) = __float2bfloat16(x - __bfloat162float(hh));
    }

    float bias_r[8];
#pragma unroll
    for (int nt = 0; nt < 4; nt++) {
        int n = wid * 32 + nt * 8 + (lane & 3) * 2;
        bias_r[nt * 2 + 0] = b_hh[n];
        bias_r[nt * 2 + 1] = b_hh[n + 1];
    }

    auto loadWm = [&](int st, int ch) {
#pragma unroll
        for (int i = 0; i < 8; i++) {
            int seg = tid + i * 256;
            int row = seg >> 3;
            int c16 = seg & 7;
            cp16(sb + R_WM + st * 32768 + SWZ128(row * 128 + c16 * 16),
                 whh_m + (size_t)row * NH + ch * 64 + c16 * 8, true);
        }
        cp_commit();
    };

    loadWm(0, 0);
    cp_wait0();
    __syncthreads();

    float acc_out[4][4];
#pragma unroll
    for (int a = 0; a < 4; a++)
#pragma unroll
        for (int d = 0; d < 4; d++) acc_out[a][d] = 0.0f;

    int lrow = lane & 15;
    int lchunk = lane >> 4;
    int r0 = lane >> 2;
    int cg = 0;

    for (int s = 0; s < NS; s++) {
        float2 xpr[4][2];
#pragma unroll
        for (int nt = 0; nt < 4; nt++) {
            int n = wid * 32 + nt * 8 + (lane & 3) * 2;
            xpr[nt][0] = *(const float2*)(xp + ((size_t)(m0 + r0) * NS + s) * NH + n);
            xpr[nt][1] = *(const float2*)(xp + ((size_t)(m0 + r0 + 8) * NS + s) * NH + n);
        }
        float acc[4][4];
#pragma unroll
        for (int a = 0; a < 4; a++)
#pragma unroll
            for (int d = 0; d < 4; d++) acc[a][d] = 0.0f;

        for (int c = 0; c < 4; c++, cg++) {
            int st = cg & 1;
            if (cg + 1 < NS * 4) { loadWm((cg + 1) & 1, (cg + 1) & 3); cp_wait1(); }
            else cp_wait0();
            __syncthreads();
            uint32_t stWh = sb + R_WH + c * 32768;
            uint32_t stWm = sb + R_WM + st * 32768;
#pragma unroll
            for (int s4 = 0; s4 < 4; s4++) {
                uint32_t aoff = c * 2048 + SWZ128(lrow * 128 + (s4 * 2 + lchunk) * 16);
                uint32_t ah[4], am[4];
                LDSM4(ah, sb + R_AH + aoff);
                LDSM4(am, sb + R_AM + aoff);
                uint32_t bh[4][2], bm[4][2];
#pragma unroll
                for (int g = 0; g < 2; g++) {
                    uint32_t off = SWZ128((wid * 32 + g * 16 + lrow) * 128 + (s4 * 2 + lchunk) * 16);
                    uint32_t q[4];
                    LDSM4(q, stWh + off);
                    bh[2 * g][0] = q[0]; bh[2 * g + 1][0] = q[1];
                    bh[2 * g][1] = q[2]; bh[2 * g + 1][1] = q[3];
                    LDSM4(q, stWm + off);
                    bm[2 * g][0] = q[0]; bm[2 * g + 1][0] = q[1];
                    bm[2 * g][1] = q[2]; bm[2 * g + 1][1] = q[3];
                }
#pragma unroll
                for (int nt = 0; nt < 4; nt++) {
                    MMA_BF16(acc[nt], ah, bh[nt]);
                    MMA_BF16(acc[nt], ah, bm[nt]);
                    MMA_BF16(acc[nt], am, bh[nt]);
                }
            }
            __syncthreads();
        }

        float w0 = wns[r0 * NS + s];
        float w1 = wns[(r0 + 8) * NS + s];
#pragma unroll
        for (int nt = 0; nt < 4; nt++) {
            int n = wid * 32 + nt * 8 + (lane & 3) * 2;
            float v00 = tanhf(acc[nt][0] + xpr[nt][0].x + bias_r[nt * 2 + 0]);
            float v01 = tanhf(acc[nt][1] + xpr[nt][0].y + bias_r[nt * 2 + 1]);
            float v10 = tanhf(acc[nt][2] + xpr[nt][1].x + bias_r[nt * 2 + 0]);
            float v11 = tanhf(acc[nt][3] + xpr[nt][1].y + bias_r[nt * 2 + 1]);
            acc_out[nt][0] += v00 * w0;
            acc_out[nt][1] += v01 * w0;
            acc_out[nt][2] += v10 * w1;
            acc_out[nt][3] += v11 * w1;
            __nv_bfloat16 h00 = __float2bfloat16(v00), h01 = __float2bfloat16(v01);
            __nv_bfloat16 h10 = __float2bfloat16(v10), h11 = __float2bfloat16(v11);
            __nv_bfloat162 p0; p0.x = h00; p0.y = h01;
            __nv_bfloat162 p1; p1.x = h10; p1.y = h11;
            __nv_bfloat162 q0; q0.x = __float2bfloat16(v00 - __bfloat162float(h00));
                               q0.y = __float2bfloat16(v01 - __bfloat162float(h01));
            __nv_bfloat162 q1; q1.x = __float2bfloat16(v10 - __bfloat162float(h10));
                               q1.y = __float2bfloat16(v11 - __bfloat162float(h11));
            uint32_t off0 = (n >> 6) * 2048 + SWZ128(r0 * 128 + (n & 63) * 2);
            uint32_t off1 = (n >> 6) * 2048 + SWZ128((r0 + 8) * 128 + (n & 63) * 2);
            *(__nv_bfloat162*)(smem + R_AH + off0) = p0;
            *(__nv_bfloat162*)(smem + R_AH + off1) = p1;
            *(__nv_bfloat162*)(smem + R_AM + off0) = q0;
            *(__nv_bfloat162*)(smem + R_AM + off1) = q1;
        }
        __syncthreads();
    }

#pragma unroll
    for (int nt = 0; nt < 4; nt++) {
        int n = wid * 32 + nt * 8 + (lane & 3) * 2;
#pragma unroll
        for (int rr = 0; rr < 2; rr++) {
            int m = m0 + r0 + rr * 8;
            float v0 = acc_out[nt][rr * 2 + 0];
            float v1 = acc_out[nt][rr * 2 + 1];
            __nv_bfloat16 h0b = __float2bfloat16(v0), h1b = __float2bfloat16(v1);
            fh[(size_t)m * 3 * NH + n] = h0b;
            fh[(size_t)m * 3 * NH + n + 1] = h1b;
            fm[(size_t)m * 3 * NH + n] = __float2bfloat16(v0 - __bfloat162float(h0b));
            fm[(size_t)m * 3 * NH + n + 1] = __float2bfloat16(v1 - __bfloat162float(h1b));
        }
    }
}

// ---------------- fused out_w2 + p_u ----------------------------------------
__global__ void outw2_pu_k(const int* __restrict__ fseq, const float* __restrict__ emb2,
                           const float* __restrict__ wn, const int* __restrict__ uid,
                           const float* __restrict__ user_emb,
                           __nv_bfloat16* __restrict__ fh, __nv_bfloat16* __restrict__ fm) {
    int b = blockIdx.x;
    int h = threadIdx.x;
    // p_u
    float x = user_emb[(size_t)uid[b] * NH + h];
    __nv_bfloat16 ph = __float2bfloat16(x);
    fh[(size_t)b * 3 * NH + NH + h] = ph;
    fm[(size_t)b * 3 * NH + NH + h] = __float2bfloat16(x - __bfloat162float(ph));
    // out_w2
    float acc = 0.0f;
    for (int s = 0; s < NS; s++) {
        int loc = fseq[b * NS + s];
        acc += emb2[(size_t)loc * NH + h] * wn[b * NS + s];
    }
    __nv_bfloat16 hh = __float2bfloat16(acc);
    fh[(size_t)b * 3 * NH + 2 * NH + h] = hh;
    fm[(size_t)b * 3 * NH + 2 * NH + h] = __float2bfloat16(acc - __bfloat162float(hh));
}

// ---------------- host launcher ---------------------------------------------
extern "C" void kernel_launch(void* const* d_in, const int* in_sizes, int n_in,
                              void* d_out, int out_size) {
    const int*   full_seq     = (const int*)d_in[0];
    const int*   full_seq_map = (const int*)d_in[1];
    const int*   length       = (const int*)d_in[2];
    const int*   user_id      = (const int*)d_in[3];
    const float* time_delta   = (const float*)d_in[4];
    const float* geo_delta    = (const float*)d_in[5];
    const float* enc_emb      = (const float*)d_in[6];
    const float* user_emb     = (const float*)d_in[7];
    const float* emb2         = (const float*)d_in[8];
    const int*   row_loc      = (const int*)d_in[9];
    const int*   col_loc      = (const int*)d_in[10];
    const float* vals_loc     = (const float*)d_in[11];
    const int*   row_usr      = (const int*)d_in[12];
    const int*   col_usr      = (const int*)d_in[13];
    const float* vals_usr     = (const float*)d_in[14];
    const float* W_ih         = (const float*)d_in[15];
    const float* W_hh         = (const float*)d_in[16];
    const float* b_ih         = (const float*)d_in[17];
    const float* b_hh         = (const float*)d_in[18];
    const float* W1           = (const float*)d_in[19];
    const float* b1           = (const float*)d_in[20];
    const float* h0           = (const float*)d_in[21];
    float* out = (float*)d_out;

    float* base = nullptr;
    cudaGetSymbolAddress((void**)&base, g_scratch);
    float* encw = base + OFF_ENCW;
    float* ewu  = base + OFF_EWU;
    __nv_bfloat16* xeh = (__nv_bfloat16*)(base + OFF_XEH);
    __nv_bfloat16* xem = (__nv_bfloat16*)(base + OFF_XEM);
    float* xp   = base + OFF_XP;
    __nv_bfloat16* w1h = (__nv_bfloat16*)(base + OFF_W1H);
    __nv_bfloat16* w1m = (__nv_bfloat16*)(base + OFF_W1M);
    __nv_bfloat16* wih = (__nv_bfloat16*)(base + OFF_WIHH);
    __nv_bfloat16* wim = (__nv_bfloat16*)(base + OFF_WIHM);
    __nv_bfloat16* whh = (__nv_bfloat16*)(base + OFF_WHHH);
    __nv_bfloat16* whm = (__nv_bfloat16*)(base + OFF_WHHM);
    __nv_bfloat16* fh  = (__nv_bfloat16*)(base + OFF_FH);
    __nv_bfloat16* fm  = (__nv_bfloat16*)(base + OFF_FM);
    float* sim  = base + OFF_SIM;
    float* wn   = base + OFF_WN;
    int*   needed = (int*)(base + OFF_NEED);

    cudaFuncSetAttribute(gemm3, cudaFuncAttributeMaxDynamicSharedMemorySize, SMEM_GEMM);
    cudaFuncSetAttribute(rnn_persist, cudaFuncAttributeMaxDynamicSharedMemorySize, SMEM_RNN);

    // idx0: zero encw+ewu and needed
    {
        int n1 = (int)(2 * (size_t)NL * NH);
        zero_all_k<<<(n1 + NU + 255) / 256, 256>>>(encw, n1, (float*)needed, NU);
    }
    // idx1
    mark_k<<<(NB + 255) / 256, 256>>>(user_id, needed);
    // idx2
    scatter_loc_k<<<(NEL * 64 + 255) / 256, 256>>>(row_loc, col_loc, vals_loc, enc_emb, encw);
    // idx3 (profiled by ncu)
    scatter_usr_k<<<(NEU * 64 + 255) / 256, 256>>>(row_usr, col_usr, vals_usr, enc_emb, ewu, needed);

    gather_sim_k<<<NB * NS / 8, 256>>>(full_seq_map, user_id, encw, ewu, xeh, xem, sim);
    weights_k<<<NB, 128>>>(time_delta, geo_delta, sim, length, wn);

    {
        int n = 2 * NH * NH + NL * 3 * NH;
        split3_k<<<(n + 255) / 256, 256>>>(W_ih, W_hh, W1, wih, wim, whh, whm, w1h, w1m);
    }

    // XP = x_emb @ W_ih^T + b_ih
    gemm3<<<dim3((NB * NS) / 128, 2), 256, SMEM_GEMM>>>(xeh, xem, wih, wim, NH, NH, xp, b_ih);

    // feat side blocks
    outw2_pu_k<<<NB, NH>>>(full_seq, emb2, wn, user_id, user_emb, fh, fm);

    // persistent RNN (fills feat cols [0, NH))
    rnn_persist<<<NB / 16, 256, SMEM_RNN>>>(whh, whm, xp, wn, b_hh, h0, fh, fm);

    // final: out = feat @ W1^T + b1
    gemm3<<<dim3(NB / 128, (NL + 127) / 128), 256, SMEM_GEMM>>>(fh, fm, w1h, w1m, NL, 3 * NH, out, b1);
}